// round 5
// baseline (speedup 1.0000x reference)
#include <cuda_runtime.h>

#define BZ   4
#define NC   256
#define L_   4096
#define P_   4356      // 66*66
#define PPAD 4480      // 35*128, padded M for GEMM1
#define EPSF 1e-7f

// Scratch: device globals (allocation-free rule)
__device__ float g_Yt[BZ][PPAD * NC];   // Y^T: [p, c], 3x3-pooled padded input
__device__ float g_inv[BZ][L_];         // 1/||x[:,l]+eps||

// ---------------------------------------------------------------------------
// invnorm[l] = 1/sqrt(sum_c (x[c,l]+eps)^2)
// ---------------------------------------------------------------------------
__global__ void k_invnorm(const float* __restrict__ x) {
    int b = blockIdx.y;
    int l = blockIdx.x * 256 + threadIdx.x;
    const float* xb = x + (size_t)b * NC * L_ + l;
    float s = 0.f;
#pragma unroll 8
    for (int c = 0; c < NC; ++c) {
        float v = xb[(size_t)c * L_] + EPSF;
        s = fmaf(v, v, s);
    }
    g_inv[b][l] = 1.0f / sqrtf(s);
}

// Zero the pad rows of Yt (p in [P_, PPAD))
__global__ void k_zeropad() {
    int b = blockIdx.y;
    int idx = blockIdx.x * 256 + threadIdx.x;   // grid.x = (PPAD-P_)*NC/256 = 124
    g_Yt[b][(size_t)P_ * NC + idx] = 0.f;
}

// ---------------------------------------------------------------------------
// Y[c,u,v] = sum_{i in {u-2..u} ∩ [0,64)} sum_{j in {v-2..v} ∩ [0,64)} x[c,i,j]
// (== 3x3 zero-padded sum pool of the zero-padded x, on the 66x66 grid)
// Stored transposed: g_Yt[b][p*NC + c], p = u*66+v
// Block: 32 channels x one u-row. 256 threads.
// ---------------------------------------------------------------------------
__global__ void k_pool(const float* __restrict__ x) {
    __shared__ float xs[32 * 193];   // [cc][ii*64+j], padded stride 193 (bank-conflict free)
    int c0 = blockIdx.x * 32;
    int u  = blockIdx.y;
    int b  = blockIdx.z;
    const float* xb = x + ((size_t)b * NC + c0) * L_;

    for (int t = threadIdx.x; t < 32 * 192; t += 256) {
        int j  = t & 63;
        int ii = (t >> 6) % 3;
        int cc = t / 192;
        int i  = u - 2 + ii;
        float v = 0.f;
        if (i >= 0 && i < 64) v = xb[(size_t)cc * L_ + i * 64 + j];
        xs[cc * 193 + ii * 64 + j] = v;
    }
    __syncthreads();

    for (int o = threadIdx.x; o < 66 * 32; o += 256) {
        int cc = o & 31;
        int v  = o >> 5;
        const float* base = &xs[cc * 193];
        float s = 0.f;
#pragma unroll
        for (int ii = 0; ii < 3; ++ii) {
#pragma unroll
            for (int dj = 0; dj < 3; ++dj) {
                int j = v - 2 + dj;
                if (j >= 0 && j < 64) s += base[ii * 64 + j];
            }
        }
        g_Yt[b][(size_t)(u * 66 + v) * NC + c0 + cc] = s;
    }
}

// ---------------------------------------------------------------------------
// Shared 8x8-per-thread FFMA micro-kernel (128x128 tile, BK=8, 256 threads)
// ---------------------------------------------------------------------------
__device__ __forceinline__ void mma_step(const float (*Asb)[128], const float (*Bsb)[128],
                                         int ty4, int tx4, float acc[8][8]) {
#pragma unroll
    for (int k = 0; k < 8; ++k) {
        float a[8], bb[8];
        *(float4*)&a[0]  = *(const float4*)&Asb[k][ty4];
        *(float4*)&a[4]  = *(const float4*)&Asb[k][ty4 + 64];
        *(float4*)&bb[0] = *(const float4*)&Bsb[k][tx4];
        *(float4*)&bb[4] = *(const float4*)&Bsb[k][tx4 + 64];
#pragma unroll
        for (int i = 0; i < 8; ++i)
#pragma unroll
            for (int j = 0; j < 8; ++j)
                acc[i][j] = fmaf(a[i], bb[j], acc[i][j]);
    }
}

// ---------------------------------------------------------------------------
// GEMM1: E[p,l] = exp( invnorm[l] * sum_c Yt[p,c] * (x[c,l]+eps) )
// M=4356(->4480 padded), N=4096, K=256. Writes unnormalized exp into att buf.
// ---------------------------------------------------------------------------
__global__ void __launch_bounds__(256, 2) k_gemm1(const float* __restrict__ x,
                                                  float* __restrict__ att) {
    const int b  = blockIdx.z;
    const int n0 = blockIdx.x * 128;
    const int m0 = blockIdx.y * 128;
    const float* A  = g_Yt[b];                       // [PPAD, 256]
    const float* B  = x + (size_t)b * NC * L_;       // [256, 4096] (+eps on load)
    float*       Cb = att + (size_t)b * P_ * L_;

    __shared__ float As[2][8][128];
    __shared__ float Bs[2][8][128];

    const int tid = threadIdx.x;
    const int ar  = tid >> 1, ak = (tid & 1) * 4;
    const int bkr = tid >> 5, bn = (tid & 31) * 4;
    const int tx4 = (tid & 15) * 4, ty4 = (tid >> 4) * 4;

    const float* Aptr = A + (size_t)(m0 + ar) * NC + ak;
    const float* Bptr = B + (size_t)bkr * L_ + n0 + bn;

    float acc[8][8];
#pragma unroll
    for (int i = 0; i < 8; ++i)
#pragma unroll
        for (int j = 0; j < 8; ++j) acc[i][j] = 0.f;

    float4 av = *(const float4*)Aptr;
    float4 bv = *(const float4*)Bptr;

    int buf = 0;
    As[0][ak + 0][ar] = av.x; As[0][ak + 1][ar] = av.y;
    As[0][ak + 2][ar] = av.z; As[0][ak + 3][ar] = av.w;
    *(float4*)&Bs[0][bkr][bn] =
        make_float4(bv.x + EPSF, bv.y + EPSF, bv.z + EPSF, bv.w + EPSF);
    __syncthreads();

    for (int kt = 1; kt < NC / 8; ++kt) {
        Aptr += 8;
        Bptr += (size_t)8 * L_;
        av = *(const float4*)Aptr;
        bv = *(const float4*)Bptr;
        mma_step(As[buf], Bs[buf], ty4, tx4, acc);
        buf ^= 1;
        As[buf][ak + 0][ar] = av.x; As[buf][ak + 1][ar] = av.y;
        As[buf][ak + 2][ar] = av.z; As[buf][ak + 3][ar] = av.w;
        *(float4*)&Bs[buf][bkr][bn] =
            make_float4(bv.x + EPSF, bv.y + EPSF, bv.z + EPSF, bv.w + EPSF);
        __syncthreads();
    }
    mma_step(As[buf], Bs[buf], ty4, tx4, acc);

    float invc[8];
    const float* ip = g_inv[b] + n0 + tx4;
    *(float4*)&invc[0] = *(const float4*)ip;
    *(float4*)&invc[4] = *(const float4*)(ip + 64);

#pragma unroll
    for (int i = 0; i < 8; ++i) {
        int r = m0 + ty4 + ((i < 4) ? i : 60 + i);
        if (r < P_) {
            float4 o0, o1;
            o0.x = __expf(acc[i][0] * invc[0]);
            o0.y = __expf(acc[i][1] * invc[1]);
            o0.z = __expf(acc[i][2] * invc[2]);
            o0.w = __expf(acc[i][3] * invc[3]);
            o1.x = __expf(acc[i][4] * invc[4]);
            o1.y = __expf(acc[i][5] * invc[5]);
            o1.z = __expf(acc[i][6] * invc[6]);
            o1.w = __expf(acc[i][7] * invc[7]);
            float* cp = Cb + (size_t)r * L_ + n0 + tx4;
            *(float4*)cp        = o0;
            *(float4*)(cp + 64) = o1;
        }
    }
}

// ---------------------------------------------------------------------------
// Row-normalize E in place: a[p,:] = E[p,:] / sum(E[p,:])  (one CTA per row)
// ---------------------------------------------------------------------------
__global__ void k_norm(float* __restrict__ att) {
    const int b = blockIdx.y;
    float4* r4 = (float4*)(att + (size_t)b * P_ * L_ + (size_t)blockIdx.x * L_);
    const int t = threadIdx.x;
    float4 v[4];
    float s = 0.f;
#pragma unroll
    for (int i = 0; i < 4; ++i) {
        v[i] = r4[t + i * 256];
        s += (v[i].x + v[i].y) + (v[i].z + v[i].w);
    }
#pragma unroll
    for (int o = 16; o > 0; o >>= 1) s += __shfl_xor_sync(0xffffffffu, s, o);
    __shared__ float red[8];
    if ((t & 31) == 0) red[t >> 5] = s;
    __syncthreads();
    float tot = ((red[0] + red[1]) + (red[2] + red[3])) +
                ((red[4] + red[5]) + (red[6] + red[7]));
    float inv = 1.0f / tot;
#pragma unroll
    for (int i = 0; i < 4; ++i) {
        v[i].x *= inv; v[i].y *= inv; v[i].z *= inv; v[i].w *= inv;
        r4[t + i * 256] = v[i];
    }
}

// ---------------------------------------------------------------------------
// GEMM2: out[c,q] = sum_l (x[c,l]+eps)*invnorm[l] * a[pq(q), l]
// M=256 (c), N=4096 (q), K=4096 (l). Row-major coalesced store into out layout.
// ---------------------------------------------------------------------------
__global__ void __launch_bounds__(256, 2) k_gemm2(const float* __restrict__ x,
                                                  const float* __restrict__ att,
                                                  float* __restrict__ out) {
    const int b  = blockIdx.z;
    const int n0 = blockIdx.x * 128;   // q
    const int m0 = blockIdx.y * 128;   // c
    const float* Ax   = x + (size_t)b * NC * L_;
    const float* Ab   = att + (size_t)b * P_ * L_;
    float*       outb = out + (size_t)b * NC * L_;

    __shared__ float As[2][8][128];
    __shared__ float Bs[2][8][128];

    const int tid = threadIdx.x;
    const int ar  = tid >> 1, ak = (tid & 1) * 4;
    const int tx4 = (tid & 15) * 4, ty4 = (tid >> 4) * 4;

    const float* Aptr = Ax + (size_t)(m0 + ar) * L_ + ak;
    const float* Iptr = g_inv[b] + ak;
    const int q  = n0 + ar;
    const int pq = ((q >> 6) + 1) * 66 + (q & 63) + 1;   // interior crop row in a
    const float* Bptr = Ab + (size_t)pq * L_ + ak;

    float acc[8][8];
#pragma unroll
    for (int i = 0; i < 8; ++i)
#pragma unroll
        for (int j = 0; j < 8; ++j) acc[i][j] = 0.f;

    float4 av = *(const float4*)Aptr;
    float4 iv = *(const float4*)Iptr;
    float4 bv = *(const float4*)Bptr;

    int buf = 0;
    As[0][ak + 0][ar] = (av.x + EPSF) * iv.x;
    As[0][ak + 1][ar] = (av.y + EPSF) * iv.y;
    As[0][ak + 2][ar] = (av.z + EPSF) * iv.z;
    As[0][ak + 3][ar] = (av.w + EPSF) * iv.w;
    Bs[0][ak + 0][ar] = bv.x; Bs[0][ak + 1][ar] = bv.y;
    Bs[0][ak + 2][ar] = bv.z; Bs[0][ak + 3][ar] = bv.w;
    __syncthreads();

    for (int kt = 1; kt < L_ / 8; ++kt) {
        Aptr += 8; Iptr += 8; Bptr += 8;
        av = *(const float4*)Aptr;
        iv = *(const float4*)Iptr;
        bv = *(const float4*)Bptr;
        mma_step(As[buf], Bs[buf], ty4, tx4, acc);
        buf ^= 1;
        As[buf][ak + 0][ar] = (av.x + EPSF) * iv.x;
        As[buf][ak + 1][ar] = (av.y + EPSF) * iv.y;
        As[buf][ak + 2][ar] = (av.z + EPSF) * iv.z;
        As[buf][ak + 3][ar] = (av.w + EPSF) * iv.w;
        Bs[buf][ak + 0][ar] = bv.x; Bs[buf][ak + 1][ar] = bv.y;
        Bs[buf][ak + 2][ar] = bv.z; Bs[buf][ak + 3][ar] = bv.w;
        __syncthreads();
    }
    mma_step(As[buf], Bs[buf], ty4, tx4, acc);

#pragma unroll
    for (int i = 0; i < 8; ++i) {
        int r = m0 + ty4 + ((i < 4) ? i : 60 + i);
        float* cp = outb + (size_t)r * L_ + n0 + tx4;
        *(float4*)cp        = make_float4(acc[i][0], acc[i][1], acc[i][2], acc[i][3]);
        *(float4*)(cp + 64) = make_float4(acc[i][4], acc[i][5], acc[i][6], acc[i][7]);
    }
}

// ---------------------------------------------------------------------------
extern "C" void kernel_launch(void* const* d_in, const int* in_sizes, int n_in,
                              void* d_out, int out_size) {
    const float* x = (const float*)d_in[0];
    float* out = (float*)d_out;
    float* att = out + (size_t)BZ * NC * L_;   // out first, then att (tuple order)

    k_invnorm<<<dim3(L_ / 256, BZ), 256>>>(x);
    k_zeropad<<<dim3((PPAD - P_) * NC / 256, BZ), 256>>>();
    k_pool<<<dim3(NC / 32, 66, BZ), 256>>>(x);
    k_gemm1<<<dim3(L_ / 128, PPAD / 128, BZ), 256>>>(x, att);
    k_norm<<<dim3(P_, BZ), 256>>>(att);
    k_gemm2<<<dim3(L_ / 128, NC / 128, BZ), 256>>>(x, att, out);
}

// round 7
// speedup vs baseline: 1.6078x; 1.6078x over previous
#include <cuda_runtime.h>
#include <cuda_bf16.h>
#include <cstdint>

#define BZ   4
#define NC   256
#define L_   4096
#define P_   4356      // 66*66
#define PPAD 4480
#define EPSF 1e-7f

// ---------------- device scratch (allocation-free rule) ----------------
__device__ float g_inv[BZ][L_];
__device__ __align__(16) __nv_bfloat16 g_YtH[(size_t)BZ * PPAD * NC];  // pooled, [p][c]
__device__ __align__(16) __nv_bfloat16 g_YtL[(size_t)BZ * PPAD * NC];
__device__ __align__(16) __nv_bfloat16 g_xTH[(size_t)BZ * L_ * NC];   // k[l][c]
__device__ __align__(16) __nv_bfloat16 g_xTL[(size_t)BZ * L_ * NC];
__device__ __align__(16) __nv_bfloat16 g_A2H[(size_t)BZ * NC * L_];   // k[c][l]
__device__ __align__(16) __nv_bfloat16 g_A2L[(size_t)BZ * NC * L_];
__device__ __align__(16) __nv_bfloat16 g_attH[(size_t)BZ * L_ * L_];  // norm. att, [q][l]
__device__ __align__(16) __nv_bfloat16 g_attL[(size_t)BZ * L_ * L_];

// ---------------- helpers ----------------
__device__ __forceinline__ uint32_t smem_u32(const void* p) {
    uint32_t a;
    asm("{ .reg .u64 t; cvta.to.shared.u64 t, %1; cvt.u32.u64 %0, t; }" : "=r"(a) : "l"(p));
    return a;
}
__device__ __forceinline__ void cp16(uint32_t s, const void* g) {
    asm volatile("cp.async.cg.shared.global [%0], [%1], 16;" :: "r"(s), "l"(g));
}
__device__ __forceinline__ void cp_commit() { asm volatile("cp.async.commit_group;" ::: "memory"); }
template <int N> __device__ __forceinline__ void cp_wait() {
    asm volatile("cp.async.wait_group %0;" :: "n"(N) : "memory");
}
__device__ __forceinline__ void ldsm4(uint32_t r[4], uint32_t a) {
    asm volatile("ldmatrix.sync.aligned.m8n8.x4.shared.b16 {%0,%1,%2,%3}, [%4];"
                 : "=r"(r[0]), "=r"(r[1]), "=r"(r[2]), "=r"(r[3]) : "r"(a));
}
__device__ __forceinline__ void mma16816(float d[4], const uint32_t a[4], const uint32_t b[2]) {
    asm volatile("mma.sync.aligned.m16n8k16.row.col.f32.bf16.bf16.f32 "
                 "{%0,%1,%2,%3}, {%4,%5,%6,%7}, {%8,%9}, {%0,%1,%2,%3};"
                 : "+f"(d[0]), "+f"(d[1]), "+f"(d[2]), "+f"(d[3])
                 : "r"(a[0]), "r"(a[1]), "r"(a[2]), "r"(a[3]), "r"(b[0]), "r"(b[1]));
}

__device__ __forceinline__ float fast_exp(float x) {
    float y = x * 1.442695040888963f;
    float n = rintf(y);
    float r = y - n;
    float p = 1.5403530393e-4f;
    p = fmaf(p, r, 1.3333558146e-3f);
    p = fmaf(p, r, 9.6181291076e-3f);
    p = fmaf(p, r, 5.5504108665e-2f);
    p = fmaf(p, r, 2.4022650696e-1f);
    p = fmaf(p, r, 6.9314718056e-1f);
    p = fmaf(p, r, 1.0f);
    return __int_as_float(__float_as_int(p) + (((int)n) << 23));
}
__device__ __forceinline__ void bsplit(float v, __nv_bfloat16& h, __nv_bfloat16& l) {
    h = __float2bfloat16(v);
    l = __float2bfloat16(v - __bfloat162float(h));
}

// ---------------- prep kernels ----------------
__global__ void k_invnorm(const float* __restrict__ x) {
    int b = blockIdx.y;
    int l = blockIdx.x * 256 + threadIdx.x;
    const float* xb = x + (size_t)b * NC * L_ + l;
    float s = 0.f;
#pragma unroll 8
    for (int c = 0; c < NC; ++c) {
        float v = xb[(size_t)c * L_] + EPSF;
        s = fmaf(v, v, s);
    }
    g_inv[b][l] = 1.0f / sqrtf(s);
}

// k[l,c] (g_xT) and k[c,l] (g_A2), bf16 hi/lo
__global__ void k_prepx(const float* __restrict__ x) {
    __shared__ float t[32][33];
    int b = blockIdx.z;
    int l0 = blockIdx.x * 32, c0 = blockIdx.y * 32;
    int tx = threadIdx.x & 31, ty = threadIdx.x >> 5;
    const float* xb = x + (size_t)b * NC * L_;
#pragma unroll
    for (int r = 0; r < 4; ++r) {
        int c = c0 + ty + r * 8;
        float v = (xb[(size_t)c * L_ + l0 + tx] + EPSF) * g_inv[b][l0 + tx];
        t[ty + r * 8][tx] = v;
        __nv_bfloat16 h, lo; bsplit(v, h, lo);
        size_t o = ((size_t)b * NC + c) * L_ + l0 + tx;
        g_A2H[o] = h; g_A2L[o] = lo;
    }
    __syncthreads();
#pragma unroll
    for (int r = 0; r < 4; ++r) {
        int l = l0 + ty + r * 8;
        float v = t[tx][ty + r * 8];
        __nv_bfloat16 h, lo; bsplit(v, h, lo);
        size_t o = ((size_t)b * L_ + l) * NC + c0 + tx;
        g_xTH[o] = h; g_xTL[o] = lo;
    }
}

__global__ void k_pool(const float* __restrict__ x) {
    __shared__ float xs[32 * 193];
    int c0 = blockIdx.x * 32;
    int u  = blockIdx.y;
    int b  = blockIdx.z;
    const float* xb = x + ((size_t)b * NC + c0) * L_;
    for (int t = threadIdx.x; t < 32 * 192; t += 256) {
        int j  = t & 63;
        int ii = (t >> 6) % 3;
        int cc = t / 192;
        int i  = u - 2 + ii;
        float v = 0.f;
        if (i >= 0 && i < 64) v = xb[(size_t)cc * L_ + i * 64 + j];
        xs[cc * 193 + ii * 64 + j] = v;
    }
    __syncthreads();
    for (int o = threadIdx.x; o < 66 * 32; o += 256) {
        int cc = o & 31;
        int v  = o >> 5;
        const float* base = &xs[cc * 193];
        float s = 0.f;
#pragma unroll
        for (int ii = 0; ii < 3; ++ii)
#pragma unroll
            for (int dj = 0; dj < 3; ++dj) {
                int j = v - 2 + dj;
                if (j >= 0 && j < 64) s += base[ii * 64 + j];
            }
        __nv_bfloat16 h, lo; bsplit(s, h, lo);
        size_t off = (size_t)b * PPAD * NC + (size_t)(u * 66 + v) * NC + c0 + cc;
        g_YtH[off] = h; g_YtL[off] = lo;
    }
}

__global__ void k_zeropad() {
    int b = blockIdx.y;
    int idx = blockIdx.x * 256 + threadIdx.x;   // grid.x = 124
    size_t o = (size_t)b * PPAD * NC + (size_t)P_ * NC + idx;
    g_YtH[o] = __float2bfloat16(0.f);
    g_YtL[o] = __float2bfloat16(0.f);
}

// ---------------- mma.sync GEMM core ----------------
// CTA tile 128x128, K-stage 32, 8 warps (warp tile 32x64), cp.async double buffer.
// Smem tiles: rows of 64B data + 16B pad (stride 80B = 5x16B -> LDSM conflict-free).
#define SROW   80
#define TILEB  10240     // 128 * 80
#define STAGEB 40960     // AH AL BH BL
#define SMEM_BYTES 81920 // 2 stages

template <int KT, bool DO_EXP>
__device__ __forceinline__ void gemm_body(const char* aH, const char* aL,
                                          const char* bH, const char* bL,
                                          size_t sA, size_t sB,
                                          float* obase, int rowOff, int rowLimit,
                                          int colOff) {
    extern __shared__ __align__(16) char dsm[];
    const int tid  = threadIdx.x;
    const int lane = tid & 31, wid = tid >> 5;
    const int wm = (wid & 3) * 32;   // warp m offset
    const int wn = (wid >> 2) * 64;  // warp n offset
    const uint32_t sb = smem_u32(dsm);

    float acc[2][8][4];
#pragma unroll
    for (int mt = 0; mt < 2; ++mt)
#pragma unroll
        for (int nt = 0; nt < 8; ++nt)
#pragma unroll
            for (int i = 0; i < 4; ++i) acc[mt][nt][i] = 0.f;

    auto issue = [&](int kt, int st) {
#pragma unroll
        for (int i = 0; i < 2; ++i) {
            int c = tid + i * 256;
            int row = c >> 2, col = (c & 3) * 16;
            uint32_t so = sb + st * STAGEB + row * SROW + col;
            size_t ga = (size_t)row * sA + (size_t)kt * 64 + col;
            size_t gb = (size_t)row * sB + (size_t)kt * 64 + col;
            cp16(so,             aH + ga);
            cp16(so + TILEB,     aL + ga);
            cp16(so + 2 * TILEB, bH + gb);
            cp16(so + 3 * TILEB, bL + gb);
        }
    };

    auto compute = [&](int st) {
        uint32_t base = sb + st * STAGEB;
#pragma unroll
        for (int ks = 0; ks < 2; ++ks) {
            uint32_t ah[2][4], al[2][4], bhf[8][2], blf[8][2];
#pragma unroll
            for (int mt = 0; mt < 2; ++mt) {
                uint32_t ad = base + (wm + mt * 16 + (lane & 15)) * SROW
                            + ks * 32 + (lane >> 4) * 16;
                ldsm4(ah[mt], ad);
                ldsm4(al[mt], ad + TILEB);
            }
#pragma unroll
            for (int np = 0; np < 4; ++np) {
                uint32_t bd = base + 2 * TILEB + (wn + np * 16 + (lane & 15)) * SROW
                            + ks * 32 + (lane >> 4) * 16;
                uint32_t t[4];
                ldsm4(t, bd);
                bhf[np * 2][0] = t[0]; bhf[np * 2][1] = t[2];
                bhf[np * 2 + 1][0] = t[1]; bhf[np * 2 + 1][1] = t[3];
                ldsm4(t, bd + TILEB);
                blf[np * 2][0] = t[0]; blf[np * 2][1] = t[2];
                blf[np * 2 + 1][0] = t[1]; blf[np * 2 + 1][1] = t[3];
            }
#pragma unroll
            for (int mt = 0; mt < 2; ++mt)
#pragma unroll
                for (int nt = 0; nt < 8; ++nt) {
                    mma16816(acc[mt][nt], ah[mt], bhf[nt]);
                    mma16816(acc[mt][nt], al[mt], bhf[nt]);
                    mma16816(acc[mt][nt], ah[mt], blf[nt]);
                }
        }
    };

    issue(0, 0);
    cp_commit();
#pragma unroll 1
    for (int kt = 0; kt < KT; ++kt) {
        if (kt + 1 < KT) {
            issue(kt + 1, (kt + 1) & 1);
            cp_commit();
            cp_wait<1>();
        } else {
            cp_wait<0>();
        }
        __syncthreads();
        compute(kt & 1);
        __syncthreads();
    }

    // epilogue: thread owns (r, c) pairs; float2 stores, coalesced in col dim
#pragma unroll
    for (int mt = 0; mt < 2; ++mt)
#pragma unroll
        for (int nt = 0; nt < 8; ++nt) {
            int r = rowOff + wm + mt * 16 + (lane >> 2);
            int c = colOff + wn + nt * 8 + (lane & 3) * 2;
            float2 v0, v1;
            if (DO_EXP) {
                v0 = make_float2(fast_exp(acc[mt][nt][0]), fast_exp(acc[mt][nt][1]));
                v1 = make_float2(fast_exp(acc[mt][nt][2]), fast_exp(acc[mt][nt][3]));
            } else {
                v0 = make_float2(acc[mt][nt][0], acc[mt][nt][1]);
                v1 = make_float2(acc[mt][nt][2], acc[mt][nt][3]);
            }
            if (r < rowLimit)     *(float2*)(obase + (size_t)r * L_ + c)       = v0;
            if (r + 8 < rowLimit) *(float2*)(obase + (size_t)(r + 8) * L_ + c) = v1;
        }
}

// GEMM1: att_raw[p][l] = exp( Yt[p,:] . k[l,:] )   (M=p, N=l, K=256)
__global__ void __launch_bounds__(256, 1) k_gemm1_mma(float* __restrict__ att) {
    int b = blockIdx.z, n0 = blockIdx.x * 128, m0 = blockIdx.y * 128;
    const char* aH = (const char*)(g_YtH + ((size_t)b * PPAD + m0) * NC);
    const char* aL = (const char*)(g_YtL + ((size_t)b * PPAD + m0) * NC);
    const char* bH = (const char*)(g_xTH + ((size_t)b * L_ + n0) * NC);
    const char* bL = (const char*)(g_xTL + ((size_t)b * L_ + n0) * NC);
    gemm_body<NC / 32, true>(aH, aL, bH, bL, (size_t)NC * 2, (size_t)NC * 2,
                             att + (size_t)b * P_ * L_, m0, P_, n0);
}

// GEMM2: out[c][q] = k[c,:] . att_q[q,:]   (M=c, N=q, K=4096)
__global__ void __launch_bounds__(256, 1) k_gemm2_mma(float* __restrict__ out) {
    int b = blockIdx.z, n0 = blockIdx.x * 128, m0 = blockIdx.y * 128;
    const char* aH = (const char*)(g_A2H + ((size_t)b * NC + m0) * L_);
    const char* aL = (const char*)(g_A2L + ((size_t)b * NC + m0) * L_);
    const char* bH = (const char*)(g_attH + ((size_t)b * L_ + n0) * L_);
    const char* bL = (const char*)(g_attL + ((size_t)b * L_ + n0) * L_);
    gemm_body<L_ / 32, false>(aH, aL, bH, bL, (size_t)L_ * 2, (size_t)L_ * 2,
                              out + (size_t)b * NC * L_, m0, 1 << 30, n0);
}

// ---------------- row-normalize + bf16 split of interior rows ----------------
__global__ void k_norm(float* __restrict__ att) {
    const int b = blockIdx.y;
    const int p = blockIdx.x;
    float4* r4 = (float4*)(att + (size_t)b * P_ * L_ + (size_t)p * L_);
    const int t = threadIdx.x;
    const int u = p / 66, vv = p % 66;
    const bool inter = (u >= 1 && u <= 64 && vv >= 1 && vv <= 64);
    __nv_bfloat16 *hr = nullptr, *lr = nullptr;
    if (inter) {
        size_t o = ((size_t)b * L_ + (size_t)((u - 1) * 64 + (vv - 1))) * L_;
        hr = g_attH + o; lr = g_attL + o;
    }
    float4 v[4];
    float s = 0.f;
#pragma unroll
    for (int i = 0; i < 4; ++i) {
        v[i] = r4[t + i * 256];
        s += (v[i].x + v[i].y) + (v[i].z + v[i].w);
    }
#pragma unroll
    for (int o = 16; o > 0; o >>= 1) s += __shfl_xor_sync(0xffffffffu, s, o);
    __shared__ float red[8];
    if ((t & 31) == 0) red[t >> 5] = s;
    __syncthreads();
    float tot = ((red[0] + red[1]) + (red[2] + red[3])) +
                ((red[4] + red[5]) + (red[6] + red[7]));
    float inv = 1.0f / tot;
#pragma unroll
    for (int i = 0; i < 4; ++i) {
        v[i].x *= inv; v[i].y *= inv; v[i].z *= inv; v[i].w *= inv;
        r4[t + i * 256] = v[i];
        if (inter) {
            int fi = t + i * 256;
            __nv_bfloat16 h0, l0, h1, l1, h2, l2, h3, l3;
            bsplit(v[i].x, h0, l0); bsplit(v[i].y, h1, l1);
            bsplit(v[i].z, h2, l2); bsplit(v[i].w, h3, l3);
            ushort4 hq, lq;
            hq.x = *(unsigned short*)&h0; hq.y = *(unsigned short*)&h1;
            hq.z = *(unsigned short*)&h2; hq.w = *(unsigned short*)&h3;
            lq.x = *(unsigned short*)&l0; lq.y = *(unsigned short*)&l1;
            lq.z = *(unsigned short*)&l2; lq.w = *(unsigned short*)&l3;
            ((ushort4*)hr)[fi] = hq;
            ((ushort4*)lr)[fi] = lq;
        }
    }
}

// ---------------------------------------------------------------------------
extern "C" void kernel_launch(void* const* d_in, const int* in_sizes, int n_in,
                              void* d_out, int out_size) {
    const float* x = (const float*)d_in[0];
    float* out = (float*)d_out;
    float* att = out + (size_t)BZ * NC * L_;   // out first, then att

    static int configured = 0;
    if (!configured) {
        cudaFuncSetAttribute(k_gemm1_mma, cudaFuncAttributeMaxDynamicSharedMemorySize, SMEM_BYTES);
        cudaFuncSetAttribute(k_gemm2_mma, cudaFuncAttributeMaxDynamicSharedMemorySize, SMEM_BYTES);
        configured = 1;
    }

    k_invnorm<<<dim3(L_ / 256, BZ), 256>>>(x);
    k_prepx<<<dim3(L_ / 32, NC / 32, BZ), 256>>>(x);
    k_pool<<<dim3(NC / 32, 66, BZ), 256>>>(x);
    k_zeropad<<<dim3(124, BZ), 256>>>();
    k_gemm1_mma<<<dim3(L_ / 128, PPAD / 128, BZ), 256, SMEM_BYTES>>>(att);
    k_norm<<<dim3(P_, BZ), 256>>>(att);
    k_gemm2_mma<<<dim3(L_ / 128, NC / 128, BZ), 256, SMEM_BYTES>>>(out);
}